// round 1
// baseline (speedup 1.0000x reference)
#include <cuda_runtime.h>
#include <math.h>

// Problem geometry (fixed by the reference's setup_inputs)
#define NB 2
#define FH 1080
#define FW 1920
#define SH 540
#define SW 960

#define NSMALL (NB*SH*SW)
#define NBIG   (NB*FH*FW)

// Fractional pixel shifts: offset * (W-1)/W
#define S1 (959.0f/960.0f)     // sobel_offset=1.0 at W=960
#define S2 (959.0f/1920.0f)    // kernel_offset=0.5 at W=960
#define T1 (539.0f/540.0f)     // sobel_offset=1.0 at H=540
#define T2 (539.0f/1080.0f)    // kernel_offset=0.5 at H=540

// apply_warp step in pixel units: relstr * (dim-1)/dim, relstr = 0.1
#define STEPX (0.1f * 1919.0f/1920.0f)
#define STEPY (0.1f * 1079.0f/1080.0f)

// Gaussian sigma=1.0, ks=5: k = exp(-0.5*t^2), normalized
#define GW0 0.05448868454964295f
#define GW1 0.24420134200323332f
#define GW2 0.4026199468942475f

// ---- scratch (static device memory; no allocations) ----
__device__ float  g_luma[NSMALL];
__device__ float2 g_sxy [NSMALL];
__device__ float  g_edge[NSMALL];
__device__ float  g_tmp [NSMALL];
__device__ float  g_blur[NSMALL];
__device__ float2 g_kxy [NSMALL];
__device__ float2 g_gs  [NSMALL];
__device__ float2 g_gf  [NBIG];

__device__ __forceinline__ float clampf(float v, float lo, float hi) {
    return fminf(fmaxf(v, lo), hi);
}

// 1-D bilinear sample along a row, border clamp (matches grid_sample semantics)
__device__ __forceinline__ float sample_row(const float* __restrict__ row, float xs, int W) {
    xs = clampf(xs, 0.0f, (float)(W - 1));
    float x0f = floorf(xs);
    int i0 = (int)x0f;
    int i1 = min(i0 + 1, W - 1);
    float w = xs - x0f;
    return row[i0] * (1.0f - w) + row[i1] * w;
}

// ---- 1. fused luma + bilinear resize 1080x1920 -> 540x960 ----
__global__ void k_luma_resize(const float* __restrict__ img) {
    int idx = blockIdx.x * blockDim.x + threadIdx.x;
    if (idx >= NSMALL) return;
    int x = idx % SW;
    int y = (idx / SW) % SH;
    int b = idx / (SW * SH);

    float px = clampf((float)x * (1919.0f / 959.0f), 0.0f, 1919.0f);
    float py = clampf((float)y * (1079.0f / 539.0f), 0.0f, 1079.0f);
    float x0f = floorf(px), y0f = floorf(py);
    int i0 = (int)x0f, j0 = (int)y0f;
    int i1 = min(i0 + 1, FW - 1), j1 = min(j0 + 1, FH - 1);
    float wx = px - x0f, wy = py - y0f;

    const float* r = img + (size_t)b * 3 * FH * FW;
    const float* g = r + FH * FW;
    const float* bb = g + FH * FW;

    int o00 = j0 * FW + i0, o01 = j0 * FW + i1, o10 = j1 * FW + i0, o11 = j1 * FW + i1;
    float v00 = 0.299f * r[o00] + 0.587f * g[o00] + 0.114f * bb[o00];
    float v01 = 0.299f * r[o01] + 0.587f * g[o01] + 0.114f * bb[o01];
    float v10 = 0.299f * r[o10] + 0.587f * g[o10] + 0.114f * bb[o10];
    float v11 = 0.299f * r[o11] + 0.587f * g[o11] + 0.114f * bb[o11];

    g_luma[idx] = (v00 * (1.0f - wx) + v01 * wx) * (1.0f - wy)
                + (v10 * (1.0f - wx) + v11 * wx) * wy;
}

// ---- 2/6. sobel_x: fractional x-shift left/right, 2-channel output ----
template<bool FIRST>
__global__ void k_sobelx() {
    int idx = blockIdx.x * blockDim.x + threadIdx.x;
    if (idx >= NSMALL) return;
    const float* src = FIRST ? g_luma : g_blur;
    float2* dst = FIRST ? g_sxy : g_kxy;
    const float s = FIRST ? S1 : S2;

    int x = idx % SW;
    int by = idx / SW;               // b*SH + y
    const float* row = src + by * SW;

    float c = row[x];
    float l = sample_row(row, (float)x - s, SW);
    float r = sample_row(row, (float)x + s, SW);
    dst[idx] = make_float2(r - l, l + 2.0f * c + r);   // [-left+right, left+2c+right]
}

// ---- 3/7. sobel_y: fractional y-shift; magnitude (pass1) or vector (pass2) ----
template<bool MAG>
__global__ void k_sobely() {
    int idx = blockIdx.x * blockDim.x + threadIdx.x;
    if (idx >= NSMALL) return;
    const float2* src = MAG ? g_sxy : g_kxy;
    const float t = MAG ? T1 : T2;

    int x = idx % SW;
    int y = (idx / SW) % SH;
    int b = idx / (SW * SH);
    const float2* plane = src + b * SH * SW;

    // top = shift by -t
    float ys = clampf((float)y - t, 0.0f, (float)(SH - 1));
    float y0f = floorf(ys);
    int j0 = (int)y0f, j1 = min(j0 + 1, SH - 1);
    float w = ys - y0f;
    float2 a = plane[j0 * SW + x], bv = plane[j1 * SW + x];
    float2 top = make_float2(a.x * (1.0f - w) + bv.x * w, a.y * (1.0f - w) + bv.y * w);

    // bot = shift by +t
    ys = clampf((float)y + t, 0.0f, (float)(SH - 1));
    y0f = floorf(ys);
    j0 = (int)y0f; j1 = min(j0 + 1, SH - 1);
    w = ys - y0f;
    a = plane[j0 * SW + x]; bv = plane[j1 * SW + x];
    float2 bot = make_float2(a.x * (1.0f - w) + bv.x * w, a.y * (1.0f - w) + bv.y * w);

    float2 c = plane[y * SW + x];
    float xg = (top.x + 2.0f * c.x + bot.x) * 0.125f;
    float yg = (bot.y - top.y) * 0.125f;

    if (MAG) {
        g_edge[idx] = powf(xg * xg + yg * yg, 0.35f);   // sqrt(.)^0.7
    } else {
        g_gs[idx] = make_float2(xg, yg);
    }
}

// ---- 4/5. separable 5-tap gaussian, replicate padding ----
__global__ void k_blur_h() {
    int idx = blockIdx.x * blockDim.x + threadIdx.x;
    if (idx >= NSMALL) return;
    int x = idx % SW;
    int by = idx / SW;
    const float* row = g_edge + by * SW;
    float v = GW0 * row[max(x - 2, 0)] + GW1 * row[max(x - 1, 0)]
            + GW2 * row[x]
            + GW1 * row[min(x + 1, SW - 1)] + GW0 * row[min(x + 2, SW - 1)];
    g_tmp[idx] = v;
}

__global__ void k_blur_v() {
    int idx = blockIdx.x * blockDim.x + threadIdx.x;
    if (idx >= NSMALL) return;
    int x = idx % SW;
    int y = (idx / SW) % SH;
    int b = idx / (SW * SH);
    const float* plane = g_tmp + b * SH * SW;
    float v = GW0 * plane[max(y - 2, 0) * SW + x] + GW1 * plane[max(y - 1, 0) * SW + x]
            + GW2 * plane[y * SW + x]
            + GW1 * plane[min(y + 1, SH - 1) * SW + x] + GW0 * plane[min(y + 2, SH - 1) * SW + x];
    g_blur[idx] = v;
}

// ---- 8. bilinear upsample grad field 540x960 -> 1080x1920 (materialized!) ----
__global__ void k_upsample() {
    int idx = blockIdx.x * blockDim.x + threadIdx.x;
    if (idx >= NBIG) return;
    int x = idx % FW;
    int y = (idx / FW) % FH;
    int b = idx / (FW * FH);

    float px = clampf((float)x * (959.0f / 1919.0f), 0.0f, (float)(SW - 1));
    float py = clampf((float)y * (539.0f / 1079.0f), 0.0f, (float)(SH - 1));
    float x0f = floorf(px), y0f = floorf(py);
    int i0 = (int)x0f, j0 = (int)y0f;
    int i1 = min(i0 + 1, SW - 1), j1 = min(j0 + 1, SH - 1);
    float wx = px - x0f, wy = py - y0f;

    const float2* p = g_gs + b * SH * SW;
    float2 v00 = p[j0 * SW + i0], v01 = p[j0 * SW + i1];
    float2 v10 = p[j1 * SW + i0], v11 = p[j1 * SW + i1];

    float gx = (v00.x * (1.0f - wx) + v01.x * wx) * (1.0f - wy)
             + (v10.x * (1.0f - wx) + v11.x * wx) * wy;
    float gy = (v00.y * (1.0f - wx) + v01.y * wx) * (1.0f - wy)
             + (v10.y * (1.0f - wx) + v11.y * wx) * wy;
    g_gf[idx] = make_float2(gx, gy);
}

// ---- 9. per-pixel 6-iteration warp walk + 3-channel image gather + clip ----
__global__ void k_warp(const float* __restrict__ img, float* __restrict__ out) {
    int idx = blockIdx.x * blockDim.x + threadIdx.x;
    if (idx >= NBIG) return;
    int x = idx % FW;
    int y = (idx / FW) % FH;
    int b = idx / (FW * FH);

    const float2* gf = g_gf + (size_t)b * FH * FW;
    float px = (float)x;
    float py = (float)y;

    #pragma unroll
    for (int it = 0; it < 6; ++it) {
        float sx = clampf(px, 0.0f, (float)(FW - 1));
        float sy = clampf(py, 0.0f, (float)(FH - 1));
        float x0f = floorf(sx), y0f = floorf(sy);
        int i0 = (int)x0f, j0 = (int)y0f;
        int i1 = min(i0 + 1, FW - 1), j1 = min(j0 + 1, FH - 1);
        float wx = sx - x0f, wy = sy - y0f;

        float2 v00 = gf[j0 * FW + i0], v01 = gf[j0 * FW + i1];
        float2 v10 = gf[j1 * FW + i0], v11 = gf[j1 * FW + i1];

        float dnx = (v00.x * (1.0f - wx) + v01.x * wx) * (1.0f - wy)
                  + (v10.x * (1.0f - wx) + v11.x * wx) * wy;
        float dny = (v00.y * (1.0f - wx) + v01.y * wx) * (1.0f - wy)
                  + (v10.y * (1.0f - wx) + v11.y * wx) * wy;

        float inv = 1.0f / (sqrtf(dnx * dnx + dny * dny) + 0.01f);
        px -= dnx * inv * STEPX;
        py -= dny * inv * STEPY;
    }

    // final image sample (shared weights across channels)
    float sx = clampf(px, 0.0f, (float)(FW - 1));
    float sy = clampf(py, 0.0f, (float)(FH - 1));
    float x0f = floorf(sx), y0f = floorf(sy);
    int i0 = (int)x0f, j0 = (int)y0f;
    int i1 = min(i0 + 1, FW - 1), j1 = min(j0 + 1, FH - 1);
    float wx = sx - x0f, wy = sy - y0f;
    float w00 = (1.0f - wx) * (1.0f - wy), w01 = wx * (1.0f - wy);
    float w10 = (1.0f - wx) * wy,          w11 = wx * wy;
    int o00 = j0 * FW + i0, o01 = j0 * FW + i1, o10 = j1 * FW + i0, o11 = j1 * FW + i1;

    const float* base = img + (size_t)b * 3 * FH * FW;
    float* obase = out + (size_t)b * 3 * FH * FW + (size_t)y * FW + x;
    #pragma unroll
    for (int c = 0; c < 3; ++c) {
        const float* plane = base + (size_t)c * FH * FW;
        float v = plane[o00] * w00 + plane[o01] * w01 + plane[o10] * w10 + plane[o11] * w11;
        obase[(size_t)c * FH * FW] = clampf(v, 0.0f, 1.0f);
    }
}

extern "C" void kernel_launch(void* const* d_in, const int* in_sizes, int n_in,
                              void* d_out, int out_size) {
    const float* img = (const float*)d_in[0];
    float* out = (float*)d_out;

    const int TB = 256;
    int gsmall = (NSMALL + TB - 1) / TB;
    int gbig   = (NBIG + TB - 1) / TB;

    k_luma_resize<<<gsmall, TB>>>(img);
    k_sobelx<true><<<gsmall, TB>>>();
    k_sobely<true><<<gsmall, TB>>>();
    k_blur_h<<<gsmall, TB>>>();
    k_blur_v<<<gsmall, TB>>>();
    k_sobelx<false><<<gsmall, TB>>>();
    k_sobely<false><<<gsmall, TB>>>();
    k_upsample<<<gbig, TB>>>();
    k_warp<<<gbig, TB>>>(img, out);
}